// round 10
// baseline (speedup 1.0000x reference)
#include <cuda_runtime.h>

// GRU: B=4096, T=512, I=32, H=64. out = final hidden (B, H) fp32.
// 128 CTAs x 384 threads, 12 warps:
//   w=8..11 (h-warps, hi-wid => arbiter priority): warp s owns rows 8s..8s+7
//     with the FULL 64-k recurrent GEMM + gate epilogue + HD writes.
//     No cross-warp exchange (rows are independent streams).
//   w=0..7 (x-warps, 2 per SMSP): compute XP(t+1) (x-projection) for 4 rows
//     each, one step ahead; self-contained XD staging (stager == reader warp).
// ONE named barrier per step (XP handoff x->h).
// Plain duplicated layout k*S_DUP + 2*row (S_DUP=68; collision-free, and
// 68*c mod 32 already spreads epilogue writes across banks 4-way).
// Math: packed fma.rn.f32x2 on duplicated smem operands.

#define THREADS      384
#define ROWS_PER_CTA 32
#define I_DIM        32
#define H_DIM        64
#define G_DIM        192
#define S_DUP        68

#define WS_FLOATS    (96 * G_DIM)       // 18432
#define HD_FLOATS    (H_DIM * S_DUP)    // 4352
#define XD_FLOATS    (I_DIM * S_DUP)    // 2176 (x2 buffers)
#define XP_U64       (2 * 4 * 8 * 3 * 32)   // parity, smsp, row, acc, lane
#define SMEM_BYTES   ((WS_FLOATS + HD_FLOATS + 2 * XD_FLOATS) * 4 + XP_U64 * 8)

typedef unsigned long long u64;

__device__ __forceinline__ void fma2(u64& d, u64 a, u64 b) {
    asm("fma.rn.f32x2 %0, %1, %2, %0;" : "+l"(d) : "l"(a), "l"(b));
}
__device__ __forceinline__ u64 add2(u64 a, u64 b) {
    u64 r;
    asm("add.rn.f32x2 %0, %1, %2;" : "=l"(r) : "l"(a), "l"(b));
    return r;
}
__device__ __forceinline__ float2 upk(u64 v) {
    float2 f;
    asm("mov.b64 {%0, %1}, %2;" : "=f"(f.x), "=f"(f.y) : "l"(v));
    return f;
}
__device__ __forceinline__ float tanh_hw(float x) {
    float y;
    asm("tanh.approx.f32 %0, %1;" : "=f"(y) : "f"(x));
    return y;
}
__device__ __forceinline__ float sig_hw(float x) {
    return fmaf(tanh_hw(0.5f * x), 0.5f, 0.5f);
}
__device__ __forceinline__ float tanh_acc(float x) {
    return __fdividef(2.0f, 1.0f + __expf(-2.0f * x)) - 1.0f;
}
__device__ __forceinline__ void barx(int id) {
    asm volatile("bar.sync %0, %1;" :: "r"(id), "r"(96) : "memory");
}

struct GateB { float bR0, bR1, bZ0, bZ1, bIN0, bIN1, bHN0, bHN1; };

__device__ __forceinline__ void gate_row(u64 sR, u64 sZ, u64 sN, u64 sX,
                                         const GateB& b, float2& h01) {
    float2 uR = upk(sR), uZ = upk(sZ), uH = upk(sN), uX = upk(sX);
    float r0g = sig_hw(uR.x + b.bR0);
    float z0g = sig_hw(uZ.x + b.bZ0);
    float n0  = tanh_acc(uX.x + b.bIN0 + r0g * (uH.x + b.bHN0));
    float r1g = sig_hw(uR.y + b.bR1);
    float z1g = sig_hw(uZ.y + b.bZ1);
    float n1  = tanh_acc(uX.y + b.bIN1 + r1g * (uH.y + b.bHN1));
    h01.x = n0 + z0g * (h01.x - n0);
    h01.y = n1 + z1g * (h01.y - n1);
}

// h k-step: 8 rows; hb = &HD[k*S_DUP + 2*r0], wb = &Ws[k*G_DIM + j0]
#define KH(hb, wb, q)                                                        \
    {                                                                        \
        ulonglong2 A0 = *reinterpret_cast<const ulonglong2*>((hb) + (q) * S_DUP);      \
        ulonglong2 A1 = *reinterpret_cast<const ulonglong2*>((hb) + (q) * S_DUP + 4);  \
        ulonglong2 A2 = *reinterpret_cast<const ulonglong2*>((hb) + (q) * S_DUP + 8);  \
        ulonglong2 A3 = *reinterpret_cast<const ulonglong2*>((hb) + (q) * S_DUP + 12); \
        u64 wr = *reinterpret_cast<const u64*>((wb) + (q) * G_DIM);          \
        u64 wz = *reinterpret_cast<const u64*>((wb) + (q) * G_DIM + 64);     \
        u64 wn = *reinterpret_cast<const u64*>((wb) + (q) * G_DIM + 128);    \
        fma2(aR[0], A0.x, wr); fma2(aR[1], A0.y, wr);                        \
        fma2(aR[2], A1.x, wr); fma2(aR[3], A1.y, wr);                        \
        fma2(aR[4], A2.x, wr); fma2(aR[5], A2.y, wr);                        \
        fma2(aR[6], A3.x, wr); fma2(aR[7], A3.y, wr);                        \
        fma2(aZ[0], A0.x, wz); fma2(aZ[1], A0.y, wz);                        \
        fma2(aZ[2], A1.x, wz); fma2(aZ[3], A1.y, wz);                        \
        fma2(aZ[4], A2.x, wz); fma2(aZ[5], A2.y, wz);                        \
        fma2(aZ[6], A3.x, wz); fma2(aZ[7], A3.y, wz);                        \
        fma2(aN[0], A0.x, wn); fma2(aN[1], A0.y, wn);                        \
        fma2(aN[2], A1.x, wn); fma2(aN[3], A1.y, wn);                        \
        fma2(aN[4], A2.x, wn); fma2(aN[5], A2.y, wn);                        \
        fma2(aN[6], A3.x, wn); fma2(aN[7], A3.y, wn);                        \
    }

// x k-step: 4 rows
#define KX(xb, wb, q)                                                        \
    {                                                                        \
        ulonglong2 A0 = *reinterpret_cast<const ulonglong2*>((xb) + (q) * S_DUP);      \
        ulonglong2 A1 = *reinterpret_cast<const ulonglong2*>((xb) + (q) * S_DUP + 4);  \
        u64 wr = *reinterpret_cast<const u64*>((wb) + (q) * G_DIM);          \
        u64 wz = *reinterpret_cast<const u64*>((wb) + (q) * G_DIM + 64);     \
        u64 wn = *reinterpret_cast<const u64*>((wb) + (q) * G_DIM + 128);    \
        fma2(aR[0], A0.x, wr); fma2(aR[1], A0.y, wr);                        \
        fma2(aR[2], A1.x, wr); fma2(aR[3], A1.y, wr);                        \
        fma2(aZ[0], A0.x, wz); fma2(aZ[1], A0.y, wz);                        \
        fma2(aZ[2], A1.x, wz); fma2(aZ[3], A1.y, wz);                        \
        fma2(aX[0], A0.x, wn); fma2(aX[1], A0.y, wn);                        \
        fma2(aX[2], A1.x, wn); fma2(aX[3], A1.y, wn);                        \
    }

#define XPI(p, l, a)  (((((p) * 4 + s) * 8 + (l)) * 3 + (a)) * 32 + c)

__global__ void __launch_bounds__(THREADS, 1)
gru_fwd_kernel(const float* __restrict__ seq,
               const float* __restrict__ W_ih,
               const float* __restrict__ W_hh,
               const float* __restrict__ b_ih,
               const float* __restrict__ b_hh,
               float* __restrict__ out,
               int B, int T)
{
    extern __shared__ float sm[];
    float* Ws  = sm;
    float* HD  = sm + WS_FLOATS;
    float* XD  = HD + HD_FLOATS;                 // 2 parity buffers
    u64*   XPb = (u64*)(XD + 2 * XD_FLOATS);

    const int tid = threadIdx.x;
    const int w   = tid >> 5;
    const int c   = tid & 31;
    const bool is_h = (w >= 8);
    const int s   = is_h ? (w - 8) : (w & 3);    // SMSP group
    const int half = is_h ? 0 : (w >> 2);        // x-warp half (0/1)
    const int bb  = blockIdx.x * ROWS_PER_CTA;
    const int r0  = s * 8;
    const int j0  = 2 * c;
    const int bid = 1 + s;

    // ---- one-time init ----
    for (int idx = tid; idx < G_DIM * H_DIM; idx += THREADS) {
        int gg = idx / H_DIM, k = idx % H_DIM;
        Ws[k * G_DIM + gg] = W_hh[idx];
    }
    for (int idx = tid; idx < G_DIM * I_DIM; idx += THREADS) {
        int gg = idx / I_DIM, i = idx % I_DIM;
        Ws[(H_DIM + i) * G_DIM + gg] = W_ih[idx];
    }
    for (int idx = tid; idx < HD_FLOATS; idx += THREADS) HD[idx] = 0.0f;

    GateB gb;
    gb.bR0  = b_ih[j0]      + b_hh[j0];
    gb.bR1  = b_ih[j0 + 1]  + b_hh[j0 + 1];
    gb.bZ0  = b_ih[64 + j0] + b_hh[64 + j0];
    gb.bZ1  = b_ih[65 + j0] + b_hh[65 + j0];
    gb.bIN0 = b_ih[128 + j0]; gb.bIN1 = b_ih[129 + j0];
    gb.bHN0 = b_hh[128 + j0]; gb.bHN1 = b_hh[129 + j0];

    // h-warp epilogue write bases (plain layout)
    const int hw0 = j0 * S_DUP;
    const int hw1 = (j0 + 1) * S_DUP;
    const int rr0 = 2 * r0;

    // x-warp roles
    const int q     = half * 32 + c;             // 0..63 within SMSP
    const int lrow  = r0 + (q >> 3);             // CTA-local row staged
    const int scol4 = (q & 7) * 4;
    const int xdw   = scol4 * S_DUP + 2 * lrow;  // stage base
    const int rr0x  = rr0 + 8 * half;            // x-GEMM A row base (4 rows)
    const float* xptr = seq + (size_t)(bb + lrow) * T * I_DIM + scol4;

    float2 hh[8];
    #pragma unroll
    for (int i = 0; i < 8; ++i) hh[i] = make_float2(0.f, 0.f);

    // ---- prologue (x-warps): stage x(0)->XD0, x(1)->XD1, compute XP(0) ----
    if (!is_h) {
        float4 v0 = *reinterpret_cast<const float4*>(xptr);
        #pragma unroll
        for (int i = 0; i < 4; ++i) {
            float vv = (&v0.x)[i];
            *reinterpret_cast<float2*>(&XD[xdw + i * S_DUP]) = make_float2(vv, vv);
        }
        if (T > 1) {
            float4 v1 = *reinterpret_cast<const float4*>(xptr + I_DIM);
            #pragma unroll
            for (int i = 0; i < 4; ++i) {
                float vv = (&v1.x)[i];
                *reinterpret_cast<float2*>(&XD[XD_FLOATS + xdw + i * S_DUP]) =
                    make_float2(vv, vv);
            }
        }
        __syncwarp();
        // XP(0) from XD[0]
        u64 aR[4] = {0, 0, 0, 0}, aZ[4] = {0, 0, 0, 0}, aX[4] = {0, 0, 0, 0};
        #pragma unroll 2
        for (int kb = 0; kb < I_DIM; kb += 4) {
            const float* xb = &XD[kb * S_DUP + rr0x];
            const float* wb = &Ws[(H_DIM + kb) * G_DIM + j0];
            KX(xb, wb, 0) KX(xb, wb, 1) KX(xb, wb, 2) KX(xb, wb, 3)
        }
        const int lb = 4 * half;
        #pragma unroll
        for (int i = 0; i < 4; ++i) {
            XPb[XPI(0, lb + i, 0)] = aR[i];
            XPb[XPI(0, lb + i, 1)] = aZ[i];
            XPb[XPI(0, lb + i, 2)] = aX[i];
        }
    }
    __syncthreads();

    // ---- main loop ----
    for (int t = 0; t < T; ++t) {
        const int par  = t & 1;
        const int par2 = par ^ 1;

        if (is_h) {
            // full 64-k recurrent GEMM for this warp's 8 rows
            u64 aR[8], aZ[8], aN[8];
            #pragma unroll
            for (int i = 0; i < 8; ++i) { aR[i] = 0; aZ[i] = 0; aN[i] = 0; }
            #pragma unroll 2
            for (int kb = 0; kb < H_DIM; kb += 4) {
                const float* hb = &HD[kb * S_DUP + rr0];
                const float* wb = &Ws[kb * G_DIM + j0];
                KH(hb, wb, 0) KH(hb, wb, 1) KH(hb, wb, 2) KH(hb, wb, 3)
            }
            // epilogue: own rows, own accumulators + XP(t) — no exchange
            #pragma unroll
            for (int l = 0; l < 8; ++l) {
                gate_row(add2(aR[l], XPb[XPI(par, l, 0)]),
                         add2(aZ[l], XPb[XPI(par, l, 1)]),
                         aN[l],
                         XPb[XPI(par, l, 2)], gb, hh[l]);
                const int gr2 = 2 * (r0 + l);
                *reinterpret_cast<float2*>(&HD[hw0 + gr2]) = make_float2(hh[l].x, hh[l].x);
                *reinterpret_cast<float2*>(&HD[hw1 + gr2]) = make_float2(hh[l].y, hh[l].y);
            }
        } else {
            // x-warp: prefetch x(t+2), XP(t+1) from XD[par2], stage x(t+2)->XD[par]
            float4 xn4 = make_float4(0.f, 0.f, 0.f, 0.f);
            if (t + 2 < T)
                xn4 = *reinterpret_cast<const float4*>(xptr + (size_t)(t + 2) * I_DIM);

            if (t + 1 < T) {
                u64 aR[4] = {0, 0, 0, 0}, aZ[4] = {0, 0, 0, 0}, aX[4] = {0, 0, 0, 0};
                const float* XDp = XD + par2 * XD_FLOATS;
                #pragma unroll 2
                for (int kb = 0; kb < I_DIM; kb += 4) {
                    const float* xb = &XDp[kb * S_DUP + rr0x];
                    const float* wb = &Ws[(H_DIM + kb) * G_DIM + j0];
                    KX(xb, wb, 0) KX(xb, wb, 1) KX(xb, wb, 2) KX(xb, wb, 3)
                }
                const int lb = 4 * half;
                #pragma unroll
                for (int i = 0; i < 4; ++i) {
                    XPb[XPI(par2, lb + i, 0)] = aR[i];
                    XPb[XPI(par2, lb + i, 1)] = aZ[i];
                    XPb[XPI(par2, lb + i, 2)] = aX[i];
                }
            }
            if (t + 2 < T) {
                float* XDw = XD + par * XD_FLOATS;
                #pragma unroll
                for (int i = 0; i < 4; ++i) {
                    float vv = (&xn4.x)[i];
                    *reinterpret_cast<float2*>(&XDw[xdw + i * S_DUP]) = make_float2(vv, vv);
                }
            }
        }
        barx(bid);   // XP handoff (also fences HD/XD smem)
    }

    // ---- final output: h-warps own all rows ----
    if (is_h) {
        #pragma unroll
        for (int l = 0; l < 8; ++l) {
            *reinterpret_cast<float2*>(&out[(size_t)(bb + r0 + l) * H_DIM + j0]) = hh[l];
        }
    }
}

extern "C" void kernel_launch(void* const* d_in, const int* in_sizes, int n_in,
                              void* d_out, int out_size) {
    const float* seq  = (const float*)d_in[0];
    const float* W_ih = (const float*)d_in[1];
    const float* W_hh = (const float*)d_in[2];
    const float* b_ih = (const float*)d_in[3];
    const float* b_hh = (const float*)d_in[4];
    float* out = (float*)d_out;

    const int B = out_size / H_DIM;
    const int T = in_sizes[0] / (B * I_DIM);

    cudaFuncSetAttribute(gru_fwd_kernel,
                         cudaFuncAttributeMaxDynamicSharedMemorySize, SMEM_BYTES);

    const int grid = (B + ROWS_PER_CTA - 1) / ROWS_PER_CTA;
    gru_fwd_kernel<<<grid, THREADS, SMEM_BYTES>>>(seq, W_ih, W_hh, b_ih, b_hh,
                                                  out, B, T);
}

// round 11
// speedup vs baseline: 1.0762x; 1.0762x over previous
#include <cuda_runtime.h>

// GRU: B=4096, T=512, I=32, H=64. out = final hidden (B, H) fp32.
// 128 CTAs x 384 threads. Per SMSP s: 3 warps {s, 4+s, 8+s} with a BALANCED
// 3-way split of the 96 k-columns [h:64 | x:32]:
//   role0: h-k [0,32)   role1: h-k [32,64)   role2: x-k [0,32) (same step)
// Each warp: 768 FFMA2 in the GEMM phase -> all hit bar1 together.
// Epilogue rows 0-2 / 3-5 / 6-7 with 3-way SC reduce; role2 stages x(t+1)
// (XD parity double buffer; no XP pipeline buffer). Two named barriers/step.
// Math: packed fma.rn.f32x2 on duplicated smem operands.

#define THREADS      384
#define ROWS_PER_CTA 32
#define I_DIM        32
#define H_DIM        64
#define G_DIM        192
#define S_DUP        68

#define WS_FLOATS    (96 * G_DIM)       // 18432
#define HD_FLOATS    (H_DIM * S_DUP)    // 4352
#define XD_FLOATS    (I_DIM * S_DUP)    // 2176 (x2 parity buffers)
#define SC_U64       (3 * 8 * 3 * 4 * 32)   // contrib, row, acc, smsp, lane = 9216
#define SMEM_BYTES   ((WS_FLOATS + HD_FLOATS + 2 * XD_FLOATS) * 4 + SC_U64 * 8)

typedef unsigned long long u64;

__device__ __forceinline__ void fma2(u64& d, u64 a, u64 b) {
    asm("fma.rn.f32x2 %0, %1, %2, %0;" : "+l"(d) : "l"(a), "l"(b));
}
__device__ __forceinline__ u64 add2(u64 a, u64 b) {
    u64 r;
    asm("add.rn.f32x2 %0, %1, %2;" : "=l"(r) : "l"(a), "l"(b));
    return r;
}
__device__ __forceinline__ float2 upk(u64 v) {
    float2 f;
    asm("mov.b64 {%0, %1}, %2;" : "=f"(f.x), "=f"(f.y) : "l"(v));
    return f;
}
__device__ __forceinline__ float tanh_hw(float x) {
    float y;
    asm("tanh.approx.f32 %0, %1;" : "=f"(y) : "f"(x));
    return y;
}
__device__ __forceinline__ float sig_hw(float x) {
    return fmaf(tanh_hw(0.5f * x), 0.5f, 0.5f);
}
__device__ __forceinline__ float tanh_acc(float x) {
    return __fdividef(2.0f, 1.0f + __expf(-2.0f * x)) - 1.0f;
}
__device__ __forceinline__ void barx(int id) {
    asm volatile("bar.sync %0, %1;" :: "r"(id), "r"(96) : "memory");
}

struct GateB { float bR0, bR1, bZ0, bZ1, bIN0, bIN1, bHN0, bHN1; };

__device__ __forceinline__ void gate_row(u64 sR, u64 sZ, u64 sN, u64 sX,
                                         const GateB& b, float2& h01) {
    float2 uR = upk(sR), uZ = upk(sZ), uH = upk(sN), uX = upk(sX);
    float r0g = sig_hw(uR.x + b.bR0);
    float z0g = sig_hw(uZ.x + b.bZ0);
    float n0  = tanh_acc(uX.x + b.bIN0 + r0g * (uH.x + b.bHN0));
    float r1g = sig_hw(uR.y + b.bR1);
    float z1g = sig_hw(uZ.y + b.bZ1);
    float n1  = tanh_acc(uX.y + b.bIN1 + r1g * (uH.y + b.bHN1));
    h01.x = n0 + z0g * (h01.x - n0);
    h01.y = n1 + z1g * (h01.y - n1);
}

// GEMM k-step: 8 rows; ab = A base (dup layout, row offset folded),
// wb = weight base (&Ws[k*G_DIM + j0]); acc aR/aZ/aN (aN holds x-n for role2)
#define KH(ab, wb, q)                                                        \
    {                                                                        \
        ulonglong2 A0 = *reinterpret_cast<const ulonglong2*>((ab) + (q) * S_DUP);      \
        ulonglong2 A1 = *reinterpret_cast<const ulonglong2*>((ab) + (q) * S_DUP + 4);  \
        ulonglong2 A2 = *reinterpret_cast<const ulonglong2*>((ab) + (q) * S_DUP + 8);  \
        ulonglong2 A3 = *reinterpret_cast<const ulonglong2*>((ab) + (q) * S_DUP + 12); \
        u64 wr = *reinterpret_cast<const u64*>((wb) + (q) * G_DIM);          \
        u64 wz = *reinterpret_cast<const u64*>((wb) + (q) * G_DIM + 64);     \
        u64 wn = *reinterpret_cast<const u64*>((wb) + (q) * G_DIM + 128);    \
        fma2(aR[0], A0.x, wr); fma2(aR[1], A0.y, wr);                        \
        fma2(aR[2], A1.x, wr); fma2(aR[3], A1.y, wr);                        \
        fma2(aR[4], A2.x, wr); fma2(aR[5], A2.y, wr);                        \
        fma2(aR[6], A3.x, wr); fma2(aR[7], A3.y, wr);                        \
        fma2(aZ[0], A0.x, wz); fma2(aZ[1], A0.y, wz);                        \
        fma2(aZ[2], A1.x, wz); fma2(aZ[3], A1.y, wz);                        \
        fma2(aZ[4], A2.x, wz); fma2(aZ[5], A2.y, wz);                        \
        fma2(aZ[6], A3.x, wz); fma2(aZ[7], A3.y, wz);                        \
        fma2(aN[0], A0.x, wn); fma2(aN[1], A0.y, wn);                        \
        fma2(aN[2], A1.x, wn); fma2(aN[3], A1.y, wn);                        \
        fma2(aN[4], A2.x, wn); fma2(aN[5], A2.y, wn);                        \
        fma2(aN[6], A3.x, wn); fma2(aN[7], A3.y, wn);                        \
    }

// SC slot: contrib ct (0..2), row l (0..7), acc a (0..2)
#define SCI(ct, l, a)  (((((ct) * 8 + (l)) * 3 + (a)) * 4 + s) * 32 + c)

#define SHIP(ct, l)                                                          \
    SCb[SCI(ct, l, 0)] = aR[l];                                              \
    SCb[SCI(ct, l, 1)] = aZ[l];                                              \
    SCb[SCI(ct, l, 2)] = aN[l];

#define HDWR(gr, hv)                                                                \
    *reinterpret_cast<float2*>(&HD[hw0 + 2 * (gr)]) = make_float2((hv).x, (hv).x);  \
    *reinterpret_cast<float2*>(&HD[hw1 + 2 * (gr)]) = make_float2((hv).y, (hv).y);

__global__ void __launch_bounds__(THREADS, 1)
gru_fwd_kernel(const float* __restrict__ seq,
               const float* __restrict__ W_ih,
               const float* __restrict__ W_hh,
               const float* __restrict__ b_ih,
               const float* __restrict__ b_hh,
               float* __restrict__ out,
               int B, int T)
{
    extern __shared__ float sm[];
    float* Ws  = sm;
    float* HD  = sm + WS_FLOATS;
    float* XD  = HD + HD_FLOATS;                 // 2 parity buffers
    u64*   SCb = (u64*)(XD + 2 * XD_FLOATS);

    const int tid  = threadIdx.x;
    const int w    = tid >> 5;
    const int c    = tid & 31;
    const int s    = w & 3;                      // SMSP group
    const int role = w >> 2;                     // 0,1: h-halves, 2: x
    const int bb   = blockIdx.x * ROWS_PER_CTA;
    const int r0   = s * 8;
    const int j0   = 2 * c;
    const int bid  = 1 + s;

    // ---- one-time init ----
    for (int idx = tid; idx < G_DIM * H_DIM; idx += THREADS) {
        int gg = idx / H_DIM, k = idx % H_DIM;
        Ws[k * G_DIM + gg] = W_hh[idx];
    }
    for (int idx = tid; idx < G_DIM * I_DIM; idx += THREADS) {
        int gg = idx / I_DIM, i = idx % I_DIM;
        Ws[(H_DIM + i) * G_DIM + gg] = W_ih[idx];
    }
    for (int idx = tid; idx < HD_FLOATS; idx += THREADS) HD[idx] = 0.0f;

    GateB gb;
    gb.bR0  = b_ih[j0]      + b_hh[j0];
    gb.bR1  = b_ih[j0 + 1]  + b_hh[j0 + 1];
    gb.bZ0  = b_ih[64 + j0] + b_hh[64 + j0];
    gb.bZ1  = b_ih[65 + j0] + b_hh[65 + j0];
    gb.bIN0 = b_ih[128 + j0]; gb.bIN1 = b_ih[129 + j0];
    gb.bHN0 = b_hh[128 + j0]; gb.bHN1 = b_hh[129 + j0];

    const int hw0 = j0 * S_DUP;
    const int hw1 = (j0 + 1) * S_DUP;
    const int rr0 = 2 * r0;

    // role2 staging geometry: lane stages row r0+(c>>2), cols (c&3)*8 .. +8
    const int srow  = r0 + (c >> 2);
    const int scol  = (c & 3) * 8;
    const int xdw   = scol * S_DUP + 2 * srow;
    const float* xptr = seq + (size_t)(bb + srow) * T * I_DIM + scol;

    float2 hh[3];
    hh[0] = make_float2(0.f, 0.f); hh[1] = hh[0]; hh[2] = hh[0];

    // ---- prologue: role2 stages x(0) -> XD[0] ----
    if (role == 2) {
        float4 va = *reinterpret_cast<const float4*>(xptr);
        float4 vb = *reinterpret_cast<const float4*>(xptr + 4);
        float v[8] = {va.x, va.y, va.z, va.w, vb.x, vb.y, vb.z, vb.w};
        #pragma unroll
        for (int i = 0; i < 8; ++i)
            *reinterpret_cast<float2*>(&XD[xdw + i * S_DUP]) = make_float2(v[i], v[i]);
    }
    __syncthreads();

    // ---- main loop ----
    for (int t = 0; t < T; ++t) {
        const int par = t & 1;

        // role2: prefetch x(t+1) from gmem early (consumed in phase 2)
        float4 pa = make_float4(0.f, 0.f, 0.f, 0.f), pb = pa;
        if (role == 2 && t + 1 < T) {
            const float* p = xptr + (size_t)(t + 1) * I_DIM;
            pa = *reinterpret_cast<const float4*>(p);
            pb = *reinterpret_cast<const float4*>(p + 4);
        }

        // ---- phase 1: balanced GEMM (768 FFMA2 per warp) ----
        u64 aR[8], aZ[8], aN[8];
        #pragma unroll
        for (int i = 0; i < 8; ++i) { aR[i] = 0; aZ[i] = 0; aN[i] = 0; }
        {
            const float* Asrc = (role == 0) ? (HD + rr0)
                              : (role == 1) ? (HD + 32 * S_DUP + rr0)
                                            : (XD + par * XD_FLOATS + rr0);
            const float* Wb = Ws + (role * 32) * G_DIM + j0;
            #pragma unroll 2
            for (int kb = 0; kb < 32; kb += 4) {
                const float* ab = Asrc + kb * S_DUP;
                const float* wb = Wb + kb * G_DIM;
                KH(ab, wb, 0) KH(ab, wb, 1) KH(ab, wb, 2) KH(ab, wb, 3)
            }
        }

        // ship partials for rows this warp does NOT epilogue
        if (role == 0) {
            SHIP(0, 3) SHIP(0, 4) SHIP(0, 5) SHIP(0, 6) SHIP(0, 7)
        } else if (role == 1) {
            SHIP(1, 0) SHIP(1, 1) SHIP(1, 2) SHIP(1, 6) SHIP(1, 7)
        } else {
            SHIP(2, 0) SHIP(2, 1) SHIP(2, 2) SHIP(2, 3) SHIP(2, 4) SHIP(2, 5)
        }
        barx(bid);

        // ---- phase 2: epilogue (3/3/2 rows) + role2 stages x(t+1) ----
        if (role == 0) {
            #pragma unroll
            for (int l = 0; l < 3; ++l) {
                u64 sR = add2(add2(aR[l], SCb[SCI(1, l, 0)]), SCb[SCI(2, l, 0)]);
                u64 sZ = add2(add2(aZ[l], SCb[SCI(1, l, 1)]), SCb[SCI(2, l, 1)]);
                u64 sN = add2(aN[l], SCb[SCI(1, l, 2)]);
                u64 sX = SCb[SCI(2, l, 2)];
                gate_row(sR, sZ, sN, sX, gb, hh[l]);
                HDWR(r0 + l, hh[l])
            }
        } else if (role == 1) {
            #pragma unroll
            for (int l = 0; l < 3; ++l) {
                const int lr = 3 + l;
                u64 sR = add2(add2(SCb[SCI(0, lr, 0)], aR[lr]), SCb[SCI(2, lr, 0)]);
                u64 sZ = add2(add2(SCb[SCI(0, lr, 1)], aZ[lr]), SCb[SCI(2, lr, 1)]);
                u64 sN = add2(SCb[SCI(0, lr, 2)], aN[lr]);
                u64 sX = SCb[SCI(2, lr, 2)];
                gate_row(sR, sZ, sN, sX, gb, hh[l]);
                HDWR(r0 + lr, hh[l])
            }
        } else {
            #pragma unroll
            for (int l = 0; l < 2; ++l) {
                const int lr = 6 + l;
                u64 sR = add2(add2(SCb[SCI(0, lr, 0)], SCb[SCI(1, lr, 0)]), aR[lr]);
                u64 sZ = add2(add2(SCb[SCI(0, lr, 1)], SCb[SCI(1, lr, 1)]), aZ[lr]);
                u64 sN = add2(SCb[SCI(0, lr, 2)], SCb[SCI(1, lr, 2)]);
                u64 sX = aN[lr];
                gate_row(sR, sZ, sN, sX, gb, hh[l]);
                HDWR(r0 + lr, hh[l])
            }
            // stage x(t+1) -> XD[par^1]
            if (t + 1 < T) {
                float* XDw = XD + (par ^ 1) * XD_FLOATS;
                float v[8] = {pa.x, pa.y, pa.z, pa.w, pb.x, pb.y, pb.z, pb.w};
                #pragma unroll
                for (int i = 0; i < 8; ++i)
                    *reinterpret_cast<float2*>(&XDw[xdw + i * S_DUP]) =
                        make_float2(v[i], v[i]);
            }
        }
        barx(bid);
    }

    // ---- final output: owners write their rows ----
    if (role == 0) {
        *reinterpret_cast<float2*>(&out[(size_t)(bb + r0 + 0) * H_DIM + j0]) = hh[0];
        *reinterpret_cast<float2*>(&out[(size_t)(bb + r0 + 1) * H_DIM + j0]) = hh[1];
        *reinterpret_cast<float2*>(&out[(size_t)(bb + r0 + 2) * H_DIM + j0]) = hh[2];
    } else if (role == 1) {
        *reinterpret_cast<float2*>(&out[(size_t)(bb + r0 + 3) * H_DIM + j0]) = hh[0];
        *reinterpret_cast<float2*>(&out[(size_t)(bb + r0 + 4) * H_DIM + j0]) = hh[1];
        *reinterpret_cast<float2*>(&out[(size_t)(bb + r0 + 5) * H_DIM + j0]) = hh[2];
    } else {
        *reinterpret_cast<float2*>(&out[(size_t)(bb + r0 + 6) * H_DIM + j0]) = hh[0];
        *reinterpret_cast<float2*>(&out[(size_t)(bb + r0 + 7) * H_DIM + j0]) = hh[1];
    }
}

extern "C" void kernel_launch(void* const* d_in, const int* in_sizes, int n_in,
                              void* d_out, int out_size) {
    const float* seq  = (const float*)d_in[0];
    const float* W_ih = (const float*)d_in[1];
    const float* W_hh = (const float*)d_in[2];
    const float* b_ih = (const float*)d_in[3];
    const float* b_hh = (const float*)d_in[4];
    float* out = (float*)d_out;

    const int B = out_size / H_DIM;
    const int T = in_sizes[0] / (B * I_DIM);

    cudaFuncSetAttribute(gru_fwd_kernel,
                         cudaFuncAttributeMaxDynamicSharedMemorySize, SMEM_BYTES);

    const int grid = (B + ROWS_PER_CTA - 1) / ROWS_PER_CTA;
    gru_fwd_kernel<<<grid, THREADS, SMEM_BYTES>>>(seq, W_ih, W_hh, b_ih, b_hh,
                                                  out, B, T);
}